// round 13
// baseline (speedup 1.0000x reference)
#include <cuda_runtime.h>
#include <math.h>

#define BN_ 1344
#define L_ 2048
#define PNUM_ 255
#define D_ 128
#define PRED_ 96
#define ROWS_ (BN_*PNUM_)      /* 342720 = 64*5355 */
#define KHEAD_ (D_*PNUM_)      /* 32640 */
#define EPS_ 1e-5f
#define EMASCALE_ 0.7071067811865476f
#define SWR(c) ((((c)>>3)&3)*8)

__device__ float g_bufA[ROWS_*D_];
__device__ float g_bufB[ROWS_*D_];
__device__ float g_u[(size_t)BN_*KHEAD_];
__device__ float g_ema[D_*4];

__device__ __forceinline__ float2 ffma2(float2 a, float2 b, float2 c) {
    unsigned long long au = *reinterpret_cast<unsigned long long*>(&a);
    unsigned long long bu = *reinterpret_cast<unsigned long long*>(&b);
    unsigned long long cu = *reinterpret_cast<unsigned long long*>(&c);
    unsigned long long ru;
    asm("fma.rn.f32x2 %0, %1, %2, %3;" : "=l"(ru) : "l"(au), "l"(bu), "l"(cu));
    return *reinterpret_cast<float2*>(&ru);
}
__device__ __forceinline__ float2 dupp(float v){
    unsigned long long ru;
    asm("mov.b64 %0, {%1, %1};" : "=l"(ru) : "f"(v));
    return *reinterpret_cast<float2*>(&ru);
}
__device__ __forceinline__ float2 dup2(float v){ return make_float2(v,v); }
__device__ __forceinline__ float2 lo2(float4 v){ return make_float2(v.x,v.y); }
__device__ __forceinline__ float2 hi2(float4 v){ return make_float2(v.z,v.w); }

// ============ K0: EMA coefficients ============
__global__ void k0_emaparam(const float* __restrict__ delta, const float* __restrict__ alpha,
                            const float* __restrict__ beta, const float* __restrict__ gamma)
{
    int d = threadIdx.x;
    if (d < D_) {
        #pragma unroll
        for (int n = 0; n < 2; n++) {
            int i = d*2 + n;
            float p = 1.f/(1.f + expf(-delta[i]));
            float q = 1.f - p * (1.f/(1.f + expf(-alpha[i])));
            float a = p * beta[i] * gamma[i] * EMASCALE_;
            g_ema[d*4 + n*2 + 0] = q;
            g_ema[d*4 + n*2 + 1] = a;
        }
    }
}

// ============ K1: featproj 16->256->128, 512 thr, weights resident ============
// smem: w1s f2[16][128], wrs f2[16][64], w2s f2[256][64],
//       xs1 f2[16][33] (part aliases), hs f2[256][33], params
#define SM1_BYTES (16*128*8 + 16*64*8 + 256*64*8 + 16*33*8 + 256*33*8 + (256+3*128)*4)

__global__ __launch_bounds__(512, 1)
void k1_featproj(const float* __restrict__ x,
                 const float* __restrict__ w1, const float* __restrict__ b1,
                 const float* __restrict__ w2, const float* __restrict__ b2,
                 const float* __restrict__ wr, const float* __restrict__ br,
                 const float* __restrict__ g,  const float* __restrict__ be)
{
    extern __shared__ unsigned char smraw[];
    float2* w1s = (float2*)smraw;              // [16][128] natural
    float2* wrs = w1s + 16*128;                // [16][64]
    float2* w2s = wrs + 16*64;                 // [256][64]
    float2* xs1 = w2s + 256*64;                // [16][33] rowpair, stride-33 pad
    float2* hs  = xs1 + 16*33;                 // [256][33]
    float*  b1s = (float*)(hs + 256*33);       // [256]
    float*  bBs = b1s + 256;                   // [128]
    float*  gs  = bBs + 128;
    float*  bes = gs + 128;
    float2* part = xs1;                        // alias (4096 B <= 4224 B)

    int tid = threadIdx.x;
    for (int i = tid; i < 16*128; i += 512) w1s[i] = ((const float2*)w1)[i];
    for (int i = tid; i < 16*64;  i += 512) wrs[i] = ((const float2*)wr)[i];
    for (int i = tid; i < 256*64; i += 512) w2s[i] = ((const float2*)w2)[i];
    if (tid < 256) b1s[tid] = b1[tid];
    if (tid < 128) { bBs[tid] = b2[tid] + br[tid]; gs[tid] = g[tid]; bes[tid] = be[tid]; }

    int lane = tid & 31, wid = tid >> 5;
    int wcc = wid & 7, wrr = wid >> 3;         // 8 col-warps x 2 row-warps
    int rg = lane >> 1, cg = lane & 1;         // 16 rowgroups x 2 colgroups
    int cA0 = wcc*32 + cg*16;                  // phase A: 16 cols of 256
    int cpA = cA0 >> 1;
    int c0  = wcc*16 + cg*8;                   // mapping B: 8 cols of 128
    int cpB = c0 >> 1;
    int rp  = wrr*16 + rg;                     // rowpair 0..31
    int r0  = rp*2;
    __syncthreads();

    const int NTILES = ROWS_/64;               // 5355
    for (int tile = blockIdx.x; tile < NTILES; tile += gridDim.x) {
        int row0 = tile*64;
        __syncthreads();                       // guard xs1(part)/hs reuse
        {   // patch gather: 8 threads/row, 2 floats each -> xs1[q][rp].comp
            int r = tid >> 3, q = (tid & 7)*2;
            int grow = row0 + r;
            int bn = grow/255, p = grow - bn*255;
            float2 v = *(const float2*)(x + bn*L_ + p*8 + q);
            int rpp = r >> 1, pr = r & 1;
            ((float*)(xs1 + (q+0)*33 + rpp))[pr] = v.x;
            ((float*)(xs1 + (q+1)*33 + rpp))[pr] = v.y;
        }
        __syncthreads();

        // fused phase A + residual over K=16 (shared act loads)
        float2 ha[2][8], rc[2][4];
        #pragma unroll
        for (int j = 0; j < 8; j++) {
            float2 bb = *(const float2*)(b1s + cA0 + 2*j);
            ha[0][j] = bb; ha[1][j] = bb;
        }
        #pragma unroll
        for (int j = 0; j < 4; j++) {
            float2 bb = *(const float2*)(bBs + c0 + 2*j);
            rc[0][j] = bb; rc[1][j] = bb;
        }
        #pragma unroll
        for (int k = 0; k < 16; k++) {
            float2 xv = xs1[k*33 + rp];
            float2 xd0 = dupp(xv.x), xd1 = dupp(xv.y);
            #pragma unroll
            for (int jq = 0; jq < 4; jq++) {
                float4 wv = *(const float4*)(w1s + k*128 + cpA + 2*jq);
                ha[0][2*jq]   = ffma2(xd0, lo2(wv), ha[0][2*jq]);
                ha[1][2*jq]   = ffma2(xd1, lo2(wv), ha[1][2*jq]);
                ha[0][2*jq+1] = ffma2(xd0, hi2(wv), ha[0][2*jq+1]);
                ha[1][2*jq+1] = ffma2(xd1, hi2(wv), ha[1][2*jq+1]);
            }
            #pragma unroll
            for (int jq = 0; jq < 2; jq++) {
                float4 wv = *(const float4*)(wrs + k*64 + cpB + 2*jq);
                rc[0][2*jq]   = ffma2(xd0, lo2(wv), rc[0][2*jq]);
                rc[1][2*jq]   = ffma2(xd1, lo2(wv), rc[1][2*jq]);
                rc[0][2*jq+1] = ffma2(xd0, hi2(wv), rc[0][2*jq+1]);
                rc[1][2*jq+1] = ffma2(xd1, hi2(wv), rc[1][2*jq+1]);
            }
        }
        // store relu(h): per col, float2 = rows (r0, r0+1)
        #pragma unroll
        for (int j = 0; j < 8; j++) {
            int ca = cA0 + 2*j, cb = ca + 1;
            hs[ca*33 + rp] = make_float2(fmaxf(ha[0][j].x,0.f), fmaxf(ha[1][j].x,0.f));
            hs[cb*33 + rp] = make_float2(fmaxf(ha[0][j].y,0.f), fmaxf(ha[1][j].y,0.f));
        }
        __syncthreads();

        // phase B: rc += h @ w2 over K=256
        #pragma unroll 4
        for (int k = 0; k < 256; k++) {
            float2 xv = hs[k*33 + rp];
            float2 xd0 = dupp(xv.x), xd1 = dupp(xv.y);
            #pragma unroll
            for (int jq = 0; jq < 2; jq++) {
                float4 wv = *(const float4*)(w2s + k*64 + cpB + 2*jq);
                rc[0][2*jq]   = ffma2(xd0, lo2(wv), rc[0][2*jq]);
                rc[1][2*jq]   = ffma2(xd1, lo2(wv), rc[1][2*jq]);
                rc[0][2*jq+1] = ffma2(xd0, hi2(wv), rc[0][2*jq+1]);
                rc[1][2*jq+1] = ffma2(xd1, hi2(wv), rc[1][2*jq+1]);
            }
        }

        // LN partials: 8 cols in-thread, cg-pair shfl, write part[row][wcc]
        #pragma unroll
        for (int i = 0; i < 2; i++) {
            float s = 0.f, q = 0.f;
            #pragma unroll
            for (int j = 0; j < 4; j++) {
                s += rc[i][j].x + rc[i][j].y;
                q += rc[i][j].x*rc[i][j].x + rc[i][j].y*rc[i][j].y;
            }
            s += __shfl_xor_sync(0xffffffffu, s, 1);
            q += __shfl_xor_sync(0xffffffffu, q, 1);
            if (cg == 0) part[(r0+i)*8 + wcc] = make_float2(s, q);
        }
        __syncthreads();

        // epilogue: combine 8 partials, normalize, store
        float4 g0 = *(const float4*)(gs + c0);
        float4 g1 = *(const float4*)(gs + c0 + 4);
        float4 e0 = *(const float4*)(bes + c0);
        float4 e1 = *(const float4*)(bes + c0 + 4);
        #pragma unroll
        for (int i = 0; i < 2; i++) {
            float s = 0.f, q = 0.f;
            #pragma unroll
            for (int w = 0; w < 8; w += 2) {
                float4 p = *(const float4*)(part + (r0+i)*8 + w);
                s += p.x + p.z; q += p.y + p.w;
            }
            float mu = s*(1.f/128.f);
            float rs = rsqrtf(q*(1.f/128.f) - mu*mu + EPS_);
            float4 o0, o1;
            o0.x = (rc[i][0].x - mu)*rs*g0.x + e0.x;
            o0.y = (rc[i][0].y - mu)*rs*g0.y + e0.y;
            o0.z = (rc[i][1].x - mu)*rs*g0.z + e0.z;
            o0.w = (rc[i][1].y - mu)*rs*g0.w + e0.w;
            o1.x = (rc[i][2].x - mu)*rs*g1.x + e1.x;
            o1.y = (rc[i][2].y - mu)*rs*g1.y + e1.y;
            o1.z = (rc[i][3].x - mu)*rs*g1.z + e1.z;
            o1.w = (rc[i][3].y - mu)*rs*g1.w + e1.w;
            float* op = g_bufA + (size_t)(row0 + r0 + i)*D_ + c0;
            *(float4*)op       = o0;
            *(float4*)(op + 4) = o1;
        }
    }
}

// ============ K2: encoder (R11, unchanged) ============
#define SM2_BYTES (3*128*64*8 + 128*32*8)
#define G8(c) (((c)>>4)&7)

__global__ __launch_bounds__(512, 1)
void k2_encoder(const float* __restrict__ ew1, const float* __restrict__ eb1,
                const float* __restrict__ ew2, const float* __restrict__ eb2,
                const float* __restrict__ ewr, const float* __restrict__ ebr,
                const float* __restrict__ eg,  const float* __restrict__ ebe,
                int layer)
{
    extern __shared__ unsigned char smraw[];
    float2* w1s = (float2*)smraw;              // [128][64]
    float2* wrs = w1s + 128*64;
    float2* w2s = wrs + 128*64;
    float2* xs  = w2s + 128*64;                // [128][32] rowpair slots
    float2* part = xs;                         // alias (used after phase B)

    const float4* w1g4 = (const float4*)(ew1 + layer*D_*D_);
    const float4* wrg4 = (const float4*)(ewr + layer*D_*D_);
    const float4* w2g4 = (const float4*)(ew2 + layer*D_*D_);
    const float* zin  = layer ? g_bufB : g_bufA;
    float*       zout = layer ? g_bufA : g_bufB;

    int tid = threadIdx.x;
    for (int i = tid; i < 4096; i += 512) {
        ((float4*)w1s)[i] = w1g4[i];
        ((float4*)wrs)[i] = wrg4[i];
        ((float4*)w2s)[i] = w2g4[i];
    }

    int lane = tid & 31, wid = tid >> 5;
    int wcc = wid & 7, wrr = wid >> 3;
    int rg = lane >> 1, cg = lane & 1;
    int c0 = wcc*16 + cg*8;
    int cp0 = c0 >> 1;
    int rpb = wrr*16;
    int r0 = wrr*32 + rg*2;

    float2 bh[4], by[4], gv[4], bev[4];
    #pragma unroll
    for (int j = 0; j < 4; j++) {
        bh[j] = *(const float2*)(eb1 + layer*128 + c0 + 2*j);
        float2 a = *(const float2*)(eb2 + layer*128 + c0 + 2*j);
        float2 b = *(const float2*)(ebr + layer*128 + c0 + 2*j);
        by[j] = make_float2(a.x + b.x, a.y + b.y);
        gv[j]  = *(const float2*)(eg  + layer*128 + c0 + 2*j);
        bev[j] = *(const float2*)(ebe + layer*128 + c0 + 2*j);
    }

    const int NTILES = ROWS_/64;
    for (int tile = blockIdx.x; tile < NTILES; tile += gridDim.x) {
        int row0 = tile*64;
        __syncthreads();
        {
            int r = tid >> 3, q0 = (tid & 7)*16;
            int rp = r >> 1, pr = r & 1, Gc = tid & 7;
            int rps = rp ^ Gc;
            const float* src = zin + (size_t)(row0 + r)*D_ + q0;
            #pragma unroll
            for (int q4 = 0; q4 < 16; q4 += 4) {
                float4 v = *(const float4*)(src + q4);
                int c = q0 + q4;
                ((float*)(xs + (c+0)*32 + rps))[pr] = v.x;
                ((float*)(xs + (c+1)*32 + rps))[pr] = v.y;
                ((float*)(xs + (c+2)*32 + rps))[pr] = v.z;
                ((float*)(xs + (c+3)*32 + rps))[pr] = v.w;
            }
        }
        __syncthreads();

        float2 ha[2][4], rc[2][4];
        #pragma unroll
        for (int j = 0; j < 4; j++) {
            ha[0][j] = bh[j]; ha[1][j] = bh[j];
            rc[0][j] = by[j]; rc[1][j] = by[j];
        }
        #pragma unroll 4
        for (int k = 0; k < 128; k++) {
            float2 xv = xs[k*32 + rpb + (rg ^ G8(k))];
            float4 wa = *(const float4*)(w1s + k*64 + cp0);
            float4 wa2 = *(const float4*)(w1s + k*64 + cp0 + 2);
            float4 wb = *(const float4*)(wrs + k*64 + cp0);
            float4 wb2 = *(const float4*)(wrs + k*64 + cp0 + 2);
            float2 xd0 = dupp(xv.x), xd1 = dupp(xv.y);
            ha[0][0] = ffma2(xd0, lo2(wa),  ha[0][0]);
            ha[1][0] = ffma2(xd1, lo2(wa),  ha[1][0]);
            ha[0][1] = ffma2(xd0, hi2(wa),  ha[0][1]);
            ha[1][1] = ffma2(xd1, hi2(wa),  ha[1][1]);
            ha[0][2] = ffma2(xd0, lo2(wa2), ha[0][2]);
            ha[1][2] = ffma2(xd1, lo2(wa2), ha[1][2]);
            ha[0][3] = ffma2(xd0, hi2(wa2), ha[0][3]);
            ha[1][3] = ffma2(xd1, hi2(wa2), ha[1][3]);
            rc[0][0] = ffma2(xd0, lo2(wb),  rc[0][0]);
            rc[1][0] = ffma2(xd1, lo2(wb),  rc[1][0]);
            rc[0][1] = ffma2(xd0, hi2(wb),  rc[0][1]);
            rc[1][1] = ffma2(xd1, hi2(wb),  rc[1][1]);
            rc[0][2] = ffma2(xd0, lo2(wb2), rc[0][2]);
            rc[1][2] = ffma2(xd1, lo2(wb2), rc[1][2]);
            rc[0][3] = ffma2(xd0, hi2(wb2), rc[0][3]);
            rc[1][3] = ffma2(xd1, hi2(wb2), rc[1][3]);
        }
        __syncthreads();

        {
            int rps = rpb + (rg ^ wcc);
            #pragma unroll
            for (int j = 0; j < 4; j++) {
                int ca = c0 + 2*j, cb = ca + 1;
                xs[ca*32 + rps] = make_float2(fmaxf(ha[0][j].x,0.f), fmaxf(ha[1][j].x,0.f));
                xs[cb*32 + rps] = make_float2(fmaxf(ha[0][j].y,0.f), fmaxf(ha[1][j].y,0.f));
            }
        }
        __syncthreads();

        #pragma unroll 4
        for (int k = 0; k < 128; k++) {
            float2 xv = xs[k*32 + rpb + (rg ^ G8(k))];
            float4 w0 = *(const float4*)(w2s + k*64 + cp0);
            float4 w02 = *(const float4*)(w2s + k*64 + cp0 + 2);
            float2 xd0 = dupp(xv.x), xd1 = dupp(xv.y);
            rc[0][0] = ffma2(xd0, lo2(w0),  rc[0][0]);
            rc[1][0] = ffma2(xd1, lo2(w0),  rc[1][0]);
            rc[0][1] = ffma2(xd0, hi2(w0),  rc[0][1]);
            rc[1][1] = ffma2(xd1, hi2(w0),  rc[1][1]);
            rc[0][2] = ffma2(xd0, lo2(w02), rc[0][2]);
            rc[1][2] = ffma2(xd1, lo2(w02), rc[1][2]);
            rc[0][3] = ffma2(xd0, hi2(w02), rc[0][3]);
            rc[1][3] = ffma2(xd1, hi2(w02), rc[1][3]);
        }
        __syncthreads();

        #pragma unroll
        for (int i = 0; i < 2; i++) {
            float s = 0.f, q = 0.f;
            #pragma unroll
            for (int j = 0; j < 4; j++) {
                s += rc[i][j].x + rc[i][j].y;
                q += rc[i][j].x*rc[i][j].x + rc[i][j].y*rc[i][j].y;
            }
            s += __shfl_xor_sync(0xffffffffu, s, 1);
            q += __shfl_xor_sync(0xffffffffu, q, 1);
            if (cg == 0) part[(r0+i)*8 + wcc] = make_float2(s, q);
        }
        __syncthreads();

        #pragma unroll
        for (int i = 0; i < 2; i++) {
            float s = 0.f, q = 0.f;
            #pragma unroll
            for (int w = 0; w < 8; w += 2) {
                float4 p = *(const float4*)(part + (r0+i)*8 + w);
                s += p.x + p.z; q += p.y + p.w;
            }
            float mu = s*(1.f/128.f);
            float rs = rsqrtf(q*(1.f/128.f) - mu*mu + EPS_);
            float4 o0, o1;
            o0.x = (rc[i][0].x - mu)*rs*gv[0].x + bev[0].x;
            o0.y = (rc[i][0].y - mu)*rs*gv[0].y + bev[0].y;
            o0.z = (rc[i][1].x - mu)*rs*gv[1].x + bev[1].x;
            o0.w = (rc[i][1].y - mu)*rs*gv[1].y + bev[1].y;
            o1.x = (rc[i][2].x - mu)*rs*gv[2].x + bev[2].x;
            o1.y = (rc[i][2].y - mu)*rs*gv[2].y + bev[2].y;
            o1.z = (rc[i][3].x - mu)*rs*gv[3].x + bev[3].x;
            o1.w = (rc[i][3].y - mu)*rs*gv[3].y + bev[3].y;
            float* op = zout + (size_t)(row0 + r0 + i)*D_ + c0;
            *(float4*)op       = o0;
            *(float4*)(op + 4) = o1;
        }
    }
}

// ============ K4: EMA recurrence + SiLU + transpose (unchanged) ============
__global__ void k4_ema(const float* __restrict__ omega)
{
    __shared__ float tile[128*65];
    int bn = blockIdx.x, d = threadIdx.x;
    float q0 = g_ema[d*4+0], a0 = g_ema[d*4+1];
    float q1 = g_ema[d*4+2], a1 = g_ema[d*4+3];
    float om = omega[d];
    const float* src = g_bufA + (size_t)bn*PNUM_*D_ + d;
    float* dst = g_u + (size_t)bn*KHEAD_;
    float s0 = 0.f, s1 = 0.f;
    for (int chunk = 0; chunk < 4; chunk++) {
        int tbase = chunk*64;
        int tn = (PNUM_ - tbase < 64) ? (PNUM_ - tbase) : 64;
        #pragma unroll 4
        for (int i = 0; i < tn; i++) {
            float xv = src[(size_t)(tbase + i)*D_];
            s0 = fmaf(s0, q0, xv);
            s1 = fmaf(s1, q1, xv);
            float v = fmaf(om, xv, fmaf(a0, s0, a1*s1));
            tile[d*65 + i] = v * (1.f/(1.f + __expf(-v)));
        }
        __syncthreads();
        for (int i = d; i < 128*64; i += 128) {
            int dd = i >> 6, tt = i & 63;
            if (tt < tn) dst[dd*PNUM_ + tbase + tt] = tile[dd*65 + tt];
        }
        __syncthreads();
    }
}

// ============ K5: head GEMM (unchanged) ============
__global__ void k5_init(const float* __restrict__ hb, float* __restrict__ out)
{
    int i = blockIdx.x*blockDim.x + threadIdx.x;
    if (i < BN_*PRED_) out[i] = hb[i % PRED_];
}

__global__ __launch_bounds__(192, 1)
void k5_head(const float* __restrict__ hw, float* __restrict__ out)
{
    __shared__ float u2[64*64];
    __shared__ float2 ws2[64*48];
    int tid = threadIdx.x;
    int cg = tid % 24, rg = tid / 24;
    int c0 = cg*4, r0 = rg*8;
    int row0 = blockIdx.x * 64;
    int k0base = blockIdx.y * 3264;

    float2 acc[8][2];
    #pragma unroll
    for (int i = 0; i < 8; i++) { acc[i][0] = make_float2(0.f,0.f); acc[i][1] = make_float2(0.f,0.f); }

    for (int ch = 0; ch < 51; ch++) {
        int k0 = k0base + ch*64;
        __syncthreads();
        for (int idx = tid; idx < 64*16; idx += 192) {
            int r = idx >> 4, q = (idx & 15)*4;
            float4 v = *(const float4*)(g_u + (size_t)(row0 + r)*KHEAD_ + k0 + q);
            int rr = r ^ SWR(q);
            u2[(q+0)*64 + rr] = v.x;
            u2[(q+1)*64 + rr] = v.y;
            u2[(q+2)*64 + rr] = v.z;
            u2[(q+3)*64 + rr] = v.w;
        }
        for (int idx = tid; idx < 64*48; idx += 192) {
            int k = idx / 48, s = idx - k*48;
            int cp = (s % 24)*2 + s/24;
            ws2[idx] = *(const float2*)(hw + (size_t)(k0 + k)*96 + 2*cp);
        }
        __syncthreads();
        #pragma unroll 2
        for (int kk = 0; kk < 64; kk++) {
            int rx = r0 ^ SWR(kk);
            float4 xa = *(const float4*)(u2 + kk*64 + rx);
            float4 xb = *(const float4*)(u2 + kk*64 + rx + 4);
            float2 w0 = ws2[kk*48 + cg];
            float2 w1v = ws2[kk*48 + 24 + cg];
            float2 xd[8] = {dup2(xa.x),dup2(xa.y),dup2(xa.z),dup2(xa.w),
                            dup2(xb.x),dup2(xb.y),dup2(xb.z),dup2(xb.w)};
            #pragma unroll
            for (int i = 0; i < 8; i++) {
                acc[i][0] = ffma2(xd[i], w0,  acc[i][0]);
                acc[i][1] = ffma2(xd[i], w1v, acc[i][1]);
            }
        }
    }
    #pragma unroll
    for (int i = 0; i < 8; i++) {
        float* op = out + (size_t)(row0 + r0 + i)*PRED_ + c0;
        atomicAdd(op+0, acc[i][0].x);
        atomicAdd(op+1, acc[i][0].y);
        atomicAdd(op+2, acc[i][1].x);
        atomicAdd(op+3, acc[i][1].y);
    }
}

// ============ launch ============
extern "C" void kernel_launch(void* const* d_in, const int* in_sizes, int n_in,
                              void* d_out, int out_size)
{
    const float* x       = (const float*)d_in[0];
    const float* fp_w1   = (const float*)d_in[1];
    const float* fp_b1   = (const float*)d_in[2];
    const float* fp_w2   = (const float*)d_in[3];
    const float* fp_b2   = (const float*)d_in[4];
    const float* fp_wr   = (const float*)d_in[5];
    const float* fp_br   = (const float*)d_in[6];
    const float* fp_g    = (const float*)d_in[7];
    const float* fp_be   = (const float*)d_in[8];
    const float* enc_w1  = (const float*)d_in[9];
    const float* enc_b1  = (const float*)d_in[10];
    const float* enc_w2  = (const float*)d_in[11];
    const float* enc_b2  = (const float*)d_in[12];
    const float* enc_wr  = (const float*)d_in[13];
    const float* enc_br  = (const float*)d_in[14];
    const float* enc_g   = (const float*)d_in[15];
    const float* enc_be  = (const float*)d_in[16];
    const float* e_delta = (const float*)d_in[17];
    const float* e_alpha = (const float*)d_in[18];
    const float* e_beta  = (const float*)d_in[19];
    const float* e_gamma = (const float*)d_in[20];
    const float* e_omega = (const float*)d_in[21];
    const float* head_w  = (const float*)d_in[22];
    const float* head_b  = (const float*)d_in[23];
    float* out = (float*)d_out;

    cudaFuncSetAttribute(k1_featproj, cudaFuncAttributeMaxDynamicSharedMemorySize, SM1_BYTES);
    cudaFuncSetAttribute(k2_encoder,  cudaFuncAttributeMaxDynamicSharedMemorySize, SM2_BYTES);

    k0_emaparam<<<1, 128>>>(e_delta, e_alpha, e_beta, e_gamma);
    k1_featproj<<<148, 512, SM1_BYTES>>>(x, fp_w1, fp_b1, fp_w2, fp_b2, fp_wr, fp_br, fp_g, fp_be);
    k2_encoder<<<148, 512, SM2_BYTES>>>(enc_w1, enc_b1, enc_w2, enc_b2, enc_wr, enc_br, enc_g, enc_be, 0);
    k2_encoder<<<148, 512, SM2_BYTES>>>(enc_w1, enc_b1, enc_w2, enc_b2, enc_wr, enc_br, enc_g, enc_be, 1);
    k4_ema<<<BN_, 128>>>(e_omega);
    k5_init<<<(BN_*PRED_ + 255)/256, 256>>>(head_b, out);
    k5_head<<<dim3(21, 10), 192>>>(head_w, out);
}

// round 14
// speedup vs baseline: 1.5422x; 1.5422x over previous
#include <cuda_runtime.h>
#include <math.h>

#define BN_ 1344
#define L_ 2048
#define PNUM_ 255
#define D_ 128
#define PRED_ 96
#define ROWS_ (BN_*PNUM_)      /* 342720 = 64*5355 */
#define KHEAD_ (D_*PNUM_)      /* 32640 */
#define EPS_ 1e-5f
#define EMASCALE_ 0.7071067811865476f
#define SWR(c) ((((c)>>3)&3)*8)

__device__ float g_bufA[ROWS_*D_];
__device__ float g_bufB[ROWS_*D_];
__device__ float g_u[(size_t)BN_*KHEAD_];
__device__ float g_ema[D_*4];

__device__ __forceinline__ float2 ffma2(float2 a, float2 b, float2 c) {
    unsigned long long au = *reinterpret_cast<unsigned long long*>(&a);
    unsigned long long bu = *reinterpret_cast<unsigned long long*>(&b);
    unsigned long long cu = *reinterpret_cast<unsigned long long*>(&c);
    unsigned long long ru;
    asm("fma.rn.f32x2 %0, %1, %2, %3;" : "=l"(ru) : "l"(au), "l"(bu), "l"(cu));
    return *reinterpret_cast<float2*>(&ru);
}
__device__ __forceinline__ float2 dupp(float v){
    unsigned long long ru;
    asm("mov.b64 %0, {%1, %1};" : "=l"(ru) : "f"(v));
    return *reinterpret_cast<float2*>(&ru);
}
__device__ __forceinline__ float2 dup2(float v){ return make_float2(v,v); }
__device__ __forceinline__ float2 lo2(float4 v){ return make_float2(v.x,v.y); }
__device__ __forceinline__ float2 hi2(float4 v){ return make_float2(v.z,v.w); }

// ============ K0: EMA coefficients ============
__global__ void k0_emaparam(const float* __restrict__ delta, const float* __restrict__ alpha,
                            const float* __restrict__ beta, const float* __restrict__ gamma)
{
    int d = threadIdx.x;
    if (d < D_) {
        #pragma unroll
        for (int n = 0; n < 2; n++) {
            int i = d*2 + n;
            float p = 1.f/(1.f + expf(-delta[i]));
            float q = 1.f - p * (1.f/(1.f + expf(-alpha[i])));
            float a = p * beta[i] * gamma[i] * EMASCALE_;
            g_ema[d*4 + n*2 + 0] = q;
            g_ema[d*4 + n*2 + 1] = a;
        }
    }
}

// ============ K1: featproj 16->256->128, 512 thr, weights resident ============
#define SM1_BYTES (16*128*8 + 16*64*8 + 256*64*8 + 16*33*8 + 256*33*8 + (256+3*128)*4)

__global__ __launch_bounds__(512, 1)
void k1_featproj(const float* __restrict__ x,
                 const float* __restrict__ w1, const float* __restrict__ b1,
                 const float* __restrict__ w2, const float* __restrict__ b2,
                 const float* __restrict__ wr, const float* __restrict__ br,
                 const float* __restrict__ g,  const float* __restrict__ be)
{
    extern __shared__ unsigned char smraw[];
    float2* w1s = (float2*)smraw;              // [16][128] natural
    float2* wrs = w1s + 16*128;                // [16][64]
    float2* w2s = wrs + 16*64;                 // [256][64]
    float2* xs1 = w2s + 256*64;                // [16][33] rowpair, stride-33 pad
    float2* hs  = xs1 + 16*33;                 // [256][33]
    float*  b1s = (float*)(hs + 256*33);       // [256]
    float*  bBs = b1s + 256;                   // [128]
    float*  gs  = bBs + 128;
    float*  bes = gs + 128;
    float2* part = xs1;                        // alias (4096 B <= 4224 B)

    int tid = threadIdx.x;
    for (int i = tid; i < 16*128; i += 512) w1s[i] = ((const float2*)w1)[i];
    for (int i = tid; i < 16*64;  i += 512) wrs[i] = ((const float2*)wr)[i];
    for (int i = tid; i < 256*64; i += 512) w2s[i] = ((const float2*)w2)[i];
    if (tid < 256) b1s[tid] = b1[tid];
    if (tid < 128) { bBs[tid] = b2[tid] + br[tid]; gs[tid] = g[tid]; bes[tid] = be[tid]; }

    int lane = tid & 31, wid = tid >> 5;
    int wcc = wid & 7, wrr = wid >> 3;         // 8 col-warps x 2 row-warps
    int rg = lane >> 1, cg = lane & 1;         // 16 rowgroups x 2 colgroups
    int cA0 = wcc*32 + cg*16;                  // phase A: 16 cols of 256
    int cpA = cA0 >> 1;
    int c0  = wcc*16 + cg*8;                   // mapping B: 8 cols of 128
    int cpB = c0 >> 1;
    int rp  = wrr*16 + rg;                     // rowpair 0..31
    int r0  = rp*2;
    __syncthreads();

    const int NTILES = ROWS_/64;               // 5355
    for (int tile = blockIdx.x; tile < NTILES; tile += gridDim.x) {
        int row0 = tile*64;
        __syncthreads();                       // guard xs1(part)/hs reuse
        {   // patch gather: 8 threads/row, 2 floats each -> xs1[q][rp].comp
            int r = tid >> 3, q = (tid & 7)*2;
            int grow = row0 + r;
            int bn = grow/255, p = grow - bn*255;
            float2 v = *(const float2*)(x + bn*L_ + p*8 + q);
            int rpp = r >> 1, pr = r & 1;
            ((float*)(xs1 + (q+0)*33 + rpp))[pr] = v.x;
            ((float*)(xs1 + (q+1)*33 + rpp))[pr] = v.y;
        }
        __syncthreads();

        // fused phase A + residual over K=16 (shared act loads)
        float2 ha[2][8], rc[2][4];
        #pragma unroll
        for (int j = 0; j < 8; j++) {
            float2 bb = *(const float2*)(b1s + cA0 + 2*j);
            ha[0][j] = bb; ha[1][j] = bb;
        }
        #pragma unroll
        for (int j = 0; j < 4; j++) {
            float2 bb = *(const float2*)(bBs + c0 + 2*j);
            rc[0][j] = bb; rc[1][j] = bb;
        }
        #pragma unroll
        for (int k = 0; k < 16; k++) {
            float2 xv = xs1[k*33 + rp];
            float2 xd0 = dupp(xv.x), xd1 = dupp(xv.y);
            #pragma unroll
            for (int jq = 0; jq < 4; jq++) {
                float4 wv = *(const float4*)(w1s + k*128 + cpA + 2*jq);
                ha[0][2*jq]   = ffma2(xd0, lo2(wv), ha[0][2*jq]);
                ha[1][2*jq]   = ffma2(xd1, lo2(wv), ha[1][2*jq]);
                ha[0][2*jq+1] = ffma2(xd0, hi2(wv), ha[0][2*jq+1]);
                ha[1][2*jq+1] = ffma2(xd1, hi2(wv), ha[1][2*jq+1]);
            }
            #pragma unroll
            for (int jq = 0; jq < 2; jq++) {
                float4 wv = *(const float4*)(wrs + k*64 + cpB + 2*jq);
                rc[0][2*jq]   = ffma2(xd0, lo2(wv), rc[0][2*jq]);
                rc[1][2*jq]   = ffma2(xd1, lo2(wv), rc[1][2*jq]);
                rc[0][2*jq+1] = ffma2(xd0, hi2(wv), rc[0][2*jq+1]);
                rc[1][2*jq+1] = ffma2(xd1, hi2(wv), rc[1][2*jq+1]);
            }
        }
        // store relu(h): per col, float2 = rows (r0, r0+1)
        #pragma unroll
        for (int j = 0; j < 8; j++) {
            int ca = cA0 + 2*j, cb = ca + 1;
            hs[ca*33 + rp] = make_float2(fmaxf(ha[0][j].x,0.f), fmaxf(ha[1][j].x,0.f));
            hs[cb*33 + rp] = make_float2(fmaxf(ha[0][j].y,0.f), fmaxf(ha[1][j].y,0.f));
        }
        __syncthreads();

        // phase B: rc += h @ w2 over K=256
        #pragma unroll 4
        for (int k = 0; k < 256; k++) {
            float2 xv = hs[k*33 + rp];
            float2 xd0 = dupp(xv.x), xd1 = dupp(xv.y);
            #pragma unroll
            for (int jq = 0; jq < 2; jq++) {
                float4 wv = *(const float4*)(w2s + k*64 + cpB + 2*jq);
                rc[0][2*jq]   = ffma2(xd0, lo2(wv), rc[0][2*jq]);
                rc[1][2*jq]   = ffma2(xd1, lo2(wv), rc[1][2*jq]);
                rc[0][2*jq+1] = ffma2(xd0, hi2(wv), rc[0][2*jq+1]);
                rc[1][2*jq+1] = ffma2(xd1, hi2(wv), rc[1][2*jq+1]);
            }
        }

        // LN partials: 8 cols in-thread, cg-pair shfl, write part[row][wcc]
        #pragma unroll
        for (int i = 0; i < 2; i++) {
            float s = 0.f, q = 0.f;
            #pragma unroll
            for (int j = 0; j < 4; j++) {
                s += rc[i][j].x + rc[i][j].y;
                q += rc[i][j].x*rc[i][j].x + rc[i][j].y*rc[i][j].y;
            }
            s += __shfl_xor_sync(0xffffffffu, s, 1);
            q += __shfl_xor_sync(0xffffffffu, q, 1);
            if (cg == 0) part[(r0+i)*8 + wcc] = make_float2(s, q);
        }
        __syncthreads();

        // epilogue: combine 8 partials, normalize, store
        float4 g0 = *(const float4*)(gs + c0);
        float4 g1 = *(const float4*)(gs + c0 + 4);
        float4 e0 = *(const float4*)(bes + c0);
        float4 e1 = *(const float4*)(bes + c0 + 4);
        #pragma unroll
        for (int i = 0; i < 2; i++) {
            float s = 0.f, q = 0.f;
            #pragma unroll
            for (int w = 0; w < 8; w += 2) {
                float4 p = *(const float4*)(part + (r0+i)*8 + w);
                s += p.x + p.z; q += p.y + p.w;
            }
            float mu = s*(1.f/128.f);
            float rs = rsqrtf(q*(1.f/128.f) - mu*mu + EPS_);
            float4 o0, o1;
            o0.x = (rc[i][0].x - mu)*rs*g0.x + e0.x;
            o0.y = (rc[i][0].y - mu)*rs*g0.y + e0.y;
            o0.z = (rc[i][1].x - mu)*rs*g0.z + e0.z;
            o0.w = (rc[i][1].y - mu)*rs*g0.w + e0.w;
            o1.x = (rc[i][2].x - mu)*rs*g1.x + e1.x;
            o1.y = (rc[i][2].y - mu)*rs*g1.y + e1.y;
            o1.z = (rc[i][3].x - mu)*rs*g1.z + e1.z;
            o1.w = (rc[i][3].y - mu)*rs*g1.w + e1.w;
            float* op = g_bufA + (size_t)(row0 + r0 + i)*D_ + c0;
            *(float4*)op       = o0;
            *(float4*)(op + 4) = o1;
        }
    }
}

// ============ K2: encoder (R11, unchanged) ============
#define SM2_BYTES (3*128*64*8 + 128*32*8)
#define G8(c) (((c)>>4)&7)

__global__ __launch_bounds__(512, 1)
void k2_encoder(const float* __restrict__ ew1, const float* __restrict__ eb1,
                const float* __restrict__ ew2, const float* __restrict__ eb2,
                const float* __restrict__ ewr, const float* __restrict__ ebr,
                const float* __restrict__ eg,  const float* __restrict__ ebe,
                int layer)
{
    extern __shared__ unsigned char smraw[];
    float2* w1s = (float2*)smraw;              // [128][64]
    float2* wrs = w1s + 128*64;
    float2* w2s = wrs + 128*64;
    float2* xs  = w2s + 128*64;                // [128][32] rowpair slots
    float2* part = xs;                         // alias (used after phase B)

    const float4* w1g4 = (const float4*)(ew1 + layer*D_*D_);
    const float4* wrg4 = (const float4*)(ewr + layer*D_*D_);
    const float4* w2g4 = (const float4*)(ew2 + layer*D_*D_);
    const float* zin  = layer ? g_bufB : g_bufA;
    float*       zout = layer ? g_bufA : g_bufB;

    int tid = threadIdx.x;
    for (int i = tid; i < 4096; i += 512) {
        ((float4*)w1s)[i] = w1g4[i];
        ((float4*)wrs)[i] = wrg4[i];
        ((float4*)w2s)[i] = w2g4[i];
    }

    int lane = tid & 31, wid = tid >> 5;
    int wcc = wid & 7, wrr = wid >> 3;
    int rg = lane >> 1, cg = lane & 1;
    int c0 = wcc*16 + cg*8;
    int cp0 = c0 >> 1;
    int rpb = wrr*16;
    int r0 = wrr*32 + rg*2;

    float2 bh[4], by[4], gv[4], bev[4];
    #pragma unroll
    for (int j = 0; j < 4; j++) {
        bh[j] = *(const float2*)(eb1 + layer*128 + c0 + 2*j);
        float2 a = *(const float2*)(eb2 + layer*128 + c0 + 2*j);
        float2 b = *(const float2*)(ebr + layer*128 + c0 + 2*j);
        by[j] = make_float2(a.x + b.x, a.y + b.y);
        gv[j]  = *(const float2*)(eg  + layer*128 + c0 + 2*j);
        bev[j] = *(const float2*)(ebe + layer*128 + c0 + 2*j);
    }

    const int NTILES = ROWS_/64;
    for (int tile = blockIdx.x; tile < NTILES; tile += gridDim.x) {
        int row0 = tile*64;
        __syncthreads();
        {
            int r = tid >> 3, q0 = (tid & 7)*16;
            int rp = r >> 1, pr = r & 1, Gc = tid & 7;
            int rps = rp ^ Gc;
            const float* src = zin + (size_t)(row0 + r)*D_ + q0;
            #pragma unroll
            for (int q4 = 0; q4 < 16; q4 += 4) {
                float4 v = *(const float4*)(src + q4);
                int c = q0 + q4;
                ((float*)(xs + (c+0)*32 + rps))[pr] = v.x;
                ((float*)(xs + (c+1)*32 + rps))[pr] = v.y;
                ((float*)(xs + (c+2)*32 + rps))[pr] = v.z;
                ((float*)(xs + (c+3)*32 + rps))[pr] = v.w;
            }
        }
        __syncthreads();

        float2 ha[2][4], rc[2][4];
        #pragma unroll
        for (int j = 0; j < 4; j++) {
            ha[0][j] = bh[j]; ha[1][j] = bh[j];
            rc[0][j] = by[j]; rc[1][j] = by[j];
        }
        #pragma unroll 4
        for (int k = 0; k < 128; k++) {
            float2 xv = xs[k*32 + rpb + (rg ^ G8(k))];
            float4 wa = *(const float4*)(w1s + k*64 + cp0);
            float4 wa2 = *(const float4*)(w1s + k*64 + cp0 + 2);
            float4 wb = *(const float4*)(wrs + k*64 + cp0);
            float4 wb2 = *(const float4*)(wrs + k*64 + cp0 + 2);
            float2 xd0 = dupp(xv.x), xd1 = dupp(xv.y);
            ha[0][0] = ffma2(xd0, lo2(wa),  ha[0][0]);
            ha[1][0] = ffma2(xd1, lo2(wa),  ha[1][0]);
            ha[0][1] = ffma2(xd0, hi2(wa),  ha[0][1]);
            ha[1][1] = ffma2(xd1, hi2(wa),  ha[1][1]);
            ha[0][2] = ffma2(xd0, lo2(wa2), ha[0][2]);
            ha[1][2] = ffma2(xd1, lo2(wa2), ha[1][2]);
            ha[0][3] = ffma2(xd0, hi2(wa2), ha[0][3]);
            ha[1][3] = ffma2(xd1, hi2(wa2), ha[1][3]);
            rc[0][0] = ffma2(xd0, lo2(wb),  rc[0][0]);
            rc[1][0] = ffma2(xd1, lo2(wb),  rc[1][0]);
            rc[0][1] = ffma2(xd0, hi2(wb),  rc[0][1]);
            rc[1][1] = ffma2(xd1, hi2(wb),  rc[1][1]);
            rc[0][2] = ffma2(xd0, lo2(wb2), rc[0][2]);
            rc[1][2] = ffma2(xd1, lo2(wb2), rc[1][2]);
            rc[0][3] = ffma2(xd0, hi2(wb2), rc[0][3]);
            rc[1][3] = ffma2(xd1, hi2(wb2), rc[1][3]);
        }
        __syncthreads();

        {
            int rps = rpb + (rg ^ wcc);
            #pragma unroll
            for (int j = 0; j < 4; j++) {
                int ca = c0 + 2*j, cb = ca + 1;
                xs[ca*32 + rps] = make_float2(fmaxf(ha[0][j].x,0.f), fmaxf(ha[1][j].x,0.f));
                xs[cb*32 + rps] = make_float2(fmaxf(ha[0][j].y,0.f), fmaxf(ha[1][j].y,0.f));
            }
        }
        __syncthreads();

        #pragma unroll 4
        for (int k = 0; k < 128; k++) {
            float2 xv = xs[k*32 + rpb + (rg ^ G8(k))];
            float4 w0 = *(const float4*)(w2s + k*64 + cp0);
            float4 w02 = *(const float4*)(w2s + k*64 + cp0 + 2);
            float2 xd0 = dupp(xv.x), xd1 = dupp(xv.y);
            rc[0][0] = ffma2(xd0, lo2(w0),  rc[0][0]);
            rc[1][0] = ffma2(xd1, lo2(w0),  rc[1][0]);
            rc[0][1] = ffma2(xd0, hi2(w0),  rc[0][1]);
            rc[1][1] = ffma2(xd1, hi2(w0),  rc[1][1]);
            rc[0][2] = ffma2(xd0, lo2(w02), rc[0][2]);
            rc[1][2] = ffma2(xd1, lo2(w02), rc[1][2]);
            rc[0][3] = ffma2(xd0, hi2(w02), rc[0][3]);
            rc[1][3] = ffma2(xd1, hi2(w02), rc[1][3]);
        }
        __syncthreads();

        #pragma unroll
        for (int i = 0; i < 2; i++) {
            float s = 0.f, q = 0.f;
            #pragma unroll
            for (int j = 0; j < 4; j++) {
                s += rc[i][j].x + rc[i][j].y;
                q += rc[i][j].x*rc[i][j].x + rc[i][j].y*rc[i][j].y;
            }
            s += __shfl_xor_sync(0xffffffffu, s, 1);
            q += __shfl_xor_sync(0xffffffffu, q, 1);
            if (cg == 0) part[(r0+i)*8 + wcc] = make_float2(s, q);
        }
        __syncthreads();

        #pragma unroll
        for (int i = 0; i < 2; i++) {
            float s = 0.f, q = 0.f;
            #pragma unroll
            for (int w = 0; w < 8; w += 2) {
                float4 p = *(const float4*)(part + (r0+i)*8 + w);
                s += p.x + p.z; q += p.y + p.w;
            }
            float mu = s*(1.f/128.f);
            float rs = rsqrtf(q*(1.f/128.f) - mu*mu + EPS_);
            float4 o0, o1;
            o0.x = (rc[i][0].x - mu)*rs*gv[0].x + bev[0].x;
            o0.y = (rc[i][0].y - mu)*rs*gv[0].y + bev[0].y;
            o0.z = (rc[i][1].x - mu)*rs*gv[1].x + bev[1].x;
            o0.w = (rc[i][1].y - mu)*rs*gv[1].y + bev[1].y;
            o1.x = (rc[i][2].x - mu)*rs*gv[2].x + bev[2].x;
            o1.y = (rc[i][2].y - mu)*rs*gv[2].y + bev[2].y;
            o1.z = (rc[i][3].x - mu)*rs*gv[3].x + bev[3].x;
            o1.w = (rc[i][3].y - mu)*rs*gv[3].y + bev[3].y;
            float* op = zout + (size_t)(row0 + r0 + i)*D_ + c0;
            *(float4*)op       = o0;
            *(float4*)(op + 4) = o1;
        }
    }
}

// ============ K4: EMA recurrence + SiLU + transpose (unchanged) ============
__global__ void k4_ema(const float* __restrict__ omega)
{
    __shared__ float tile[128*65];
    int bn = blockIdx.x, d = threadIdx.x;
    float q0 = g_ema[d*4+0], a0 = g_ema[d*4+1];
    float q1 = g_ema[d*4+2], a1 = g_ema[d*4+3];
    float om = omega[d];
    const float* src = g_bufA + (size_t)bn*PNUM_*D_ + d;
    float* dst = g_u + (size_t)bn*KHEAD_;
    float s0 = 0.f, s1 = 0.f;
    for (int chunk = 0; chunk < 4; chunk++) {
        int tbase = chunk*64;
        int tn = (PNUM_ - tbase < 64) ? (PNUM_ - tbase) : 64;
        #pragma unroll 4
        for (int i = 0; i < tn; i++) {
            float xv = src[(size_t)(tbase + i)*D_];
            s0 = fmaf(s0, q0, xv);
            s1 = fmaf(s1, q1, xv);
            float v = fmaf(om, xv, fmaf(a0, s0, a1*s1));
            tile[d*65 + i] = v * (1.f/(1.f + __expf(-v)));
        }
        __syncthreads();
        for (int i = d; i < 128*64; i += 128) {
            int dd = i >> 6, tt = i & 63;
            if (tt < tn) dst[dd*PNUM_ + tbase + tt] = tile[dd*65 + tt];
        }
        __syncthreads();
    }
}

// ============ K5: head GEMM (unchanged) ============
__global__ void k5_init(const float* __restrict__ hb, float* __restrict__ out)
{
    int i = blockIdx.x*blockDim.x + threadIdx.x;
    if (i < BN_*PRED_) out[i] = hb[i % PRED_];
}

__global__ __launch_bounds__(192, 1)
void k5_head(const float* __restrict__ hw, float* __restrict__ out)
{
    __shared__ float u2[64*64];
    __shared__ float2 ws2[64*48];
    int tid = threadIdx.x;
    int cg = tid % 24, rg = tid / 24;
    int c0 = cg*4, r0 = rg*8;
    int row0 = blockIdx.x * 64;
    int k0base = blockIdx.y * 3264;

    float2 acc[8][2];
    #pragma unroll
    for (int i = 0; i < 8; i++) { acc[i][0] = make_float2(0.f,0.f); acc[i][1] = make_float2(0.f,0.f); }

    for (int ch = 0; ch < 51; ch++) {
        int k0 = k0base + ch*64;
        __syncthreads();
        for (int idx = tid; idx < 64*16; idx += 192) {
            int r = idx >> 4, q = (idx & 15)*4;
            float4 v = *(const float4*)(g_u + (size_t)(row0 + r)*KHEAD_ + k0 + q);
            int rr = r ^ SWR(q);
            u2[(q+0)*64 + rr] = v.x;
            u2[(q+1)*64 + rr] = v.y;
            u2[(q+2)*64 + rr] = v.z;
            u2[(q+3)*64 + rr] = v.w;
        }
        for (int idx = tid; idx < 64*48; idx += 192) {
            int k = idx / 48, s = idx - k*48;
            int cp = (s % 24)*2 + s/24;
            ws2[idx] = *(const float2*)(hw + (size_t)(k0 + k)*96 + 2*cp);
        }
        __syncthreads();
        #pragma unroll 2
        for (int kk = 0; kk < 64; kk++) {
            int rx = r0 ^ SWR(kk);
            float4 xa = *(const float4*)(u2 + kk*64 + rx);
            float4 xb = *(const float4*)(u2 + kk*64 + rx + 4);
            float2 w0 = ws2[kk*48 + cg];
            float2 w1v = ws2[kk*48 + 24 + cg];
            float2 xd[8] = {dup2(xa.x),dup2(xa.y),dup2(xa.z),dup2(xa.w),
                            dup2(xb.x),dup2(xb.y),dup2(xb.z),dup2(xb.w)};
            #pragma unroll
            for (int i = 0; i < 8; i++) {
                acc[i][0] = ffma2(xd[i], w0,  acc[i][0]);
                acc[i][1] = ffma2(xd[i], w1v, acc[i][1]);
            }
        }
    }
    #pragma unroll
    for (int i = 0; i < 8; i++) {
        float* op = out + (size_t)(row0 + r0 + i)*PRED_ + c0;
        atomicAdd(op+0, acc[i][0].x);
        atomicAdd(op+1, acc[i][0].y);
        atomicAdd(op+2, acc[i][1].x);
        atomicAdd(op+3, acc[i][1].y);
    }
}

// ============ launch ============
extern "C" void kernel_launch(void* const* d_in, const int* in_sizes, int n_in,
                              void* d_out, int out_size)
{
    const float* x       = (const float*)d_in[0];
    const float* fp_w1   = (const float*)d_in[1];
    const float* fp_b1   = (const float*)d_in[2];
    const float* fp_w2   = (const float*)d_in[3];
    const float* fp_b2   = (const float*)d_in[4];
    const float* fp_wr   = (const float*)d_in[5];
    const float* fp_br   = (const float*)d_in[6];
    const float* fp_g    = (const float*)d_in[7];
    const float* fp_be   = (const float*)d_in[8];
    const float* enc_w1  = (const float*)d_in[9];
    const float* enc_b1  = (const float*)d_in[10];
    const float* enc_w2  = (const float*)d_in[11];
    const float* enc_b2  = (const float*)d_in[12];
    const float* enc_wr  = (const float*)d_in[13];
    const float* enc_br  = (const float*)d_in[14];
    const float* enc_g   = (const float*)d_in[15];
    const float* enc_be  = (const float*)d_in[16];
    const float* e_delta = (const float*)d_in[17];
    const float* e_alpha = (const float*)d_in[18];
    const float* e_beta  = (const float*)d_in[19];
    const float* e_gamma = (const float*)d_in[20];
    const float* e_omega = (const float*)d_in[21];
    const float* head_w  = (const float*)d_in[22];
    const float* head_b  = (const float*)d_in[23];
    float* out = (float*)d_out;

    cudaFuncSetAttribute(k1_featproj, cudaFuncAttributeMaxDynamicSharedMemorySize, SM1_BYTES);
    cudaFuncSetAttribute(k2_encoder,  cudaFuncAttributeMaxDynamicSharedMemorySize, SM2_BYTES);

    k0_emaparam<<<1, 128>>>(e_delta, e_alpha, e_beta, e_gamma);
    k1_featproj<<<148, 512, SM1_BYTES>>>(x, fp_w1, fp_b1, fp_w2, fp_b2, fp_wr, fp_br, fp_g, fp_be);
    k2_encoder<<<148, 512, SM2_BYTES>>>(enc_w1, enc_b1, enc_w2, enc_b2, enc_wr, enc_br, enc_g, enc_be, 0);
    k2_encoder<<<148, 512, SM2_BYTES>>>(enc_w1, enc_b1, enc_w2, enc_b2, enc_wr, enc_br, enc_g, enc_be, 1);
    k4_ema<<<BN_, 128>>>(e_omega);
    k5_init<<<(BN_*PRED_ + 255)/256, 256>>>(head_b, out);
    k5_head<<<dim3(21, 10), 192>>>(head_w, out);
}

// round 15
// speedup vs baseline: 1.6099x; 1.0439x over previous
#include <cuda_runtime.h>
#include <math.h>

#define BN_ 1344
#define L_ 2048
#define PNUM_ 255
#define D_ 128
#define PRED_ 96
#define ROWS_ (BN_*PNUM_)      /* 342720 = 64*5355 */
#define KHEAD_ (D_*PNUM_)      /* 32640 */
#define EPS_ 1e-5f
#define EMASCALE_ 0.7071067811865476f
#define SWR(c) ((((c)>>3)&3)*8)

__device__ float g_bufA[ROWS_*D_];
__device__ float g_bufB[ROWS_*D_];
__device__ float g_u[(size_t)BN_*KHEAD_];
__device__ float g_ema[D_*4];

__device__ __forceinline__ float2 ffma2(float2 a, float2 b, float2 c) {
    unsigned long long au = *reinterpret_cast<unsigned long long*>(&a);
    unsigned long long bu = *reinterpret_cast<unsigned long long*>(&b);
    unsigned long long cu = *reinterpret_cast<unsigned long long*>(&c);
    unsigned long long ru;
    asm("fma.rn.f32x2 %0, %1, %2, %3;" : "=l"(ru) : "l"(au), "l"(bu), "l"(cu));
    return *reinterpret_cast<float2*>(&ru);
}
__device__ __forceinline__ float2 dupp(float v){
    unsigned long long ru;
    asm("mov.b64 %0, {%1, %1};" : "=l"(ru) : "f"(v));
    return *reinterpret_cast<float2*>(&ru);
}
__device__ __forceinline__ float2 dup2(float v){ return make_float2(v,v); }
__device__ __forceinline__ float2 lo2(float4 v){ return make_float2(v.x,v.y); }
__device__ __forceinline__ float2 hi2(float4 v){ return make_float2(v.z,v.w); }

// ============ K0: EMA coefficients ============
__global__ void k0_emaparam(const float* __restrict__ delta, const float* __restrict__ alpha,
                            const float* __restrict__ beta, const float* __restrict__ gamma)
{
    int d = threadIdx.x;
    if (d < D_) {
        #pragma unroll
        for (int n = 0; n < 2; n++) {
            int i = d*2 + n;
            float p = 1.f/(1.f + expf(-delta[i]));
            float q = 1.f - p * (1.f/(1.f + expf(-alpha[i])));
            float a = p * beta[i] * gamma[i] * EMASCALE_;
            g_ema[d*4 + n*2 + 0] = q;
            g_ema[d*4 + n*2 + 1] = a;
        }
    }
}

// ============ K1: featproj 16->256->128, 512 thr, weights resident ============
#define SM1_BYTES (16*128*8 + 16*64*8 + 256*64*8 + 16*33*8 + 256*33*8 + (256+3*128)*4)

__global__ __launch_bounds__(512, 1)
void k1_featproj(const float* __restrict__ x,
                 const float* __restrict__ w1, const float* __restrict__ b1,
                 const float* __restrict__ w2, const float* __restrict__ b2,
                 const float* __restrict__ wr, const float* __restrict__ br,
                 const float* __restrict__ g,  const float* __restrict__ be)
{
    extern __shared__ unsigned char smraw[];
    float2* w1s = (float2*)smraw;              // [16][128] natural
    float2* wrs = w1s + 16*128;                // [16][64]
    float2* w2s = wrs + 16*64;                 // [256][64]
    float2* xs1 = w2s + 256*64;                // [16][33] rowpair, stride-33 pad
    float2* hs  = xs1 + 16*33;                 // [256][33]
    float*  b1s = (float*)(hs + 256*33);       // [256]
    float*  bBs = b1s + 256;                   // [128]
    float*  gs  = bBs + 128;
    float*  bes = gs + 128;
    float2* part = xs1;                        // alias (4096 B <= 4224 B)

    int tid = threadIdx.x;
    for (int i = tid; i < 16*128; i += 512) w1s[i] = ((const float2*)w1)[i];
    for (int i = tid; i < 16*64;  i += 512) wrs[i] = ((const float2*)wr)[i];
    for (int i = tid; i < 256*64; i += 512) w2s[i] = ((const float2*)w2)[i];
    if (tid < 256) b1s[tid] = b1[tid];
    if (tid < 128) { bBs[tid] = b2[tid] + br[tid]; gs[tid] = g[tid]; bes[tid] = be[tid]; }

    int lane = tid & 31, wid = tid >> 5;
    int wcc = wid & 7, wrr = wid >> 3;         // 8 col-warps x 2 row-warps
    int rg = lane >> 1, cg = lane & 1;         // 16 rowgroups x 2 colgroups
    int cA0 = wcc*32 + cg*16;                  // phase A: 16 cols of 256
    int cpA = cA0 >> 1;
    int c0  = wcc*16 + cg*8;                   // mapping B: 8 cols of 128
    int cpB = c0 >> 1;
    int rp  = wrr*16 + rg;                     // rowpair 0..31
    int r0  = rp*2;
    __syncthreads();

    const int NTILES = ROWS_/64;               // 5355
    for (int tile = blockIdx.x; tile < NTILES; tile += gridDim.x) {
        int row0 = tile*64;
        __syncthreads();                       // guard xs1(part)/hs reuse
        {   // patch gather: 8 threads/row, 2 floats each -> xs1[q][rp].comp
            int r = tid >> 3, q = (tid & 7)*2;
            int grow = row0 + r;
            int bn = grow/255, p = grow - bn*255;
            float2 v = *(const float2*)(x + bn*L_ + p*8 + q);
            int rpp = r >> 1, pr = r & 1;
            ((float*)(xs1 + (q+0)*33 + rpp))[pr] = v.x;
            ((float*)(xs1 + (q+1)*33 + rpp))[pr] = v.y;
        }
        __syncthreads();

        // fused phase A + residual over K=16 (shared act loads)
        float2 ha[2][8], rc[2][4];
        #pragma unroll
        for (int j = 0; j < 8; j++) {
            float2 bb = *(const float2*)(b1s + cA0 + 2*j);
            ha[0][j] = bb; ha[1][j] = bb;
        }
        #pragma unroll
        for (int j = 0; j < 4; j++) {
            float2 bb = *(const float2*)(bBs + c0 + 2*j);
            rc[0][j] = bb; rc[1][j] = bb;
        }
        #pragma unroll
        for (int k = 0; k < 16; k++) {
            float2 xv = xs1[k*33 + rp];
            float2 xd0 = dupp(xv.x), xd1 = dupp(xv.y);
            #pragma unroll
            for (int jq = 0; jq < 4; jq++) {
                float4 wv = *(const float4*)(w1s + k*128 + cpA + 2*jq);
                ha[0][2*jq]   = ffma2(xd0, lo2(wv), ha[0][2*jq]);
                ha[1][2*jq]   = ffma2(xd1, lo2(wv), ha[1][2*jq]);
                ha[0][2*jq+1] = ffma2(xd0, hi2(wv), ha[0][2*jq+1]);
                ha[1][2*jq+1] = ffma2(xd1, hi2(wv), ha[1][2*jq+1]);
            }
            #pragma unroll
            for (int jq = 0; jq < 2; jq++) {
                float4 wv = *(const float4*)(wrs + k*64 + cpB + 2*jq);
                rc[0][2*jq]   = ffma2(xd0, lo2(wv), rc[0][2*jq]);
                rc[1][2*jq]   = ffma2(xd1, lo2(wv), rc[1][2*jq]);
                rc[0][2*jq+1] = ffma2(xd0, hi2(wv), rc[0][2*jq+1]);
                rc[1][2*jq+1] = ffma2(xd1, hi2(wv), rc[1][2*jq+1]);
            }
        }
        // store relu(h): per col, float2 = rows (r0, r0+1)
        #pragma unroll
        for (int j = 0; j < 8; j++) {
            int ca = cA0 + 2*j, cb = ca + 1;
            hs[ca*33 + rp] = make_float2(fmaxf(ha[0][j].x,0.f), fmaxf(ha[1][j].x,0.f));
            hs[cb*33 + rp] = make_float2(fmaxf(ha[0][j].y,0.f), fmaxf(ha[1][j].y,0.f));
        }
        __syncthreads();

        // phase B: rc += h @ w2 over K=256
        #pragma unroll 4
        for (int k = 0; k < 256; k++) {
            float2 xv = hs[k*33 + rp];
            float2 xd0 = dupp(xv.x), xd1 = dupp(xv.y);
            #pragma unroll
            for (int jq = 0; jq < 2; jq++) {
                float4 wv = *(const float4*)(w2s + k*64 + cpB + 2*jq);
                rc[0][2*jq]   = ffma2(xd0, lo2(wv), rc[0][2*jq]);
                rc[1][2*jq]   = ffma2(xd1, lo2(wv), rc[1][2*jq]);
                rc[0][2*jq+1] = ffma2(xd0, hi2(wv), rc[0][2*jq+1]);
                rc[1][2*jq+1] = ffma2(xd1, hi2(wv), rc[1][2*jq+1]);
            }
        }

        // LN partials: 8 cols in-thread, cg-pair shfl, write part[row][wcc]
        #pragma unroll
        for (int i = 0; i < 2; i++) {
            float s = 0.f, q = 0.f;
            #pragma unroll
            for (int j = 0; j < 4; j++) {
                s += rc[i][j].x + rc[i][j].y;
                q += rc[i][j].x*rc[i][j].x + rc[i][j].y*rc[i][j].y;
            }
            s += __shfl_xor_sync(0xffffffffu, s, 1);
            q += __shfl_xor_sync(0xffffffffu, q, 1);
            if (cg == 0) part[(r0+i)*8 + wcc] = make_float2(s, q);
        }
        __syncthreads();

        // epilogue: combine 8 partials, normalize, store
        float4 g0 = *(const float4*)(gs + c0);
        float4 g1 = *(const float4*)(gs + c0 + 4);
        float4 e0 = *(const float4*)(bes + c0);
        float4 e1 = *(const float4*)(bes + c0 + 4);
        #pragma unroll
        for (int i = 0; i < 2; i++) {
            float s = 0.f, q = 0.f;
            #pragma unroll
            for (int w = 0; w < 8; w += 2) {
                float4 p = *(const float4*)(part + (r0+i)*8 + w);
                s += p.x + p.z; q += p.y + p.w;
            }
            float mu = s*(1.f/128.f);
            float rs = rsqrtf(q*(1.f/128.f) - mu*mu + EPS_);
            float4 o0, o1;
            o0.x = (rc[i][0].x - mu)*rs*g0.x + e0.x;
            o0.y = (rc[i][0].y - mu)*rs*g0.y + e0.y;
            o0.z = (rc[i][1].x - mu)*rs*g0.z + e0.z;
            o0.w = (rc[i][1].y - mu)*rs*g0.w + e0.w;
            o1.x = (rc[i][2].x - mu)*rs*g1.x + e1.x;
            o1.y = (rc[i][2].y - mu)*rs*g1.y + e1.y;
            o1.z = (rc[i][3].x - mu)*rs*g1.z + e1.z;
            o1.w = (rc[i][3].y - mu)*rs*g1.w + e1.w;
            float* op = g_bufA + (size_t)(row0 + r0 + i)*D_ + c0;
            *(float4*)op       = o0;
            *(float4*)(op + 4) = o1;
        }
    }
}

// ============ K2: encoder (R11, unchanged) ============
#define SM2_BYTES (3*128*64*8 + 128*32*8)
#define G8(c) (((c)>>4)&7)

__global__ __launch_bounds__(512, 1)
void k2_encoder(const float* __restrict__ ew1, const float* __restrict__ eb1,
                const float* __restrict__ ew2, const float* __restrict__ eb2,
                const float* __restrict__ ewr, const float* __restrict__ ebr,
                const float* __restrict__ eg,  const float* __restrict__ ebe,
                int layer)
{
    extern __shared__ unsigned char smraw[];
    float2* w1s = (float2*)smraw;              // [128][64]
    float2* wrs = w1s + 128*64;
    float2* w2s = wrs + 128*64;
    float2* xs  = w2s + 128*64;                // [128][32] rowpair slots
    float2* part = xs;                         // alias (used after phase B)

    const float4* w1g4 = (const float4*)(ew1 + layer*D_*D_);
    const float4* wrg4 = (const float4*)(ewr + layer*D_*D_);
    const float4* w2g4 = (const float4*)(ew2 + layer*D_*D_);
    const float* zin  = layer ? g_bufB : g_bufA;
    float*       zout = layer ? g_bufA : g_bufB;

    int tid = threadIdx.x;
    for (int i = tid; i < 4096; i += 512) {
        ((float4*)w1s)[i] = w1g4[i];
        ((float4*)wrs)[i] = wrg4[i];
        ((float4*)w2s)[i] = w2g4[i];
    }

    int lane = tid & 31, wid = tid >> 5;
    int wcc = wid & 7, wrr = wid >> 3;
    int rg = lane >> 1, cg = lane & 1;
    int c0 = wcc*16 + cg*8;
    int cp0 = c0 >> 1;
    int rpb = wrr*16;
    int r0 = wrr*32 + rg*2;

    float2 bh[4], by[4], gv[4], bev[4];
    #pragma unroll
    for (int j = 0; j < 4; j++) {
        bh[j] = *(const float2*)(eb1 + layer*128 + c0 + 2*j);
        float2 a = *(const float2*)(eb2 + layer*128 + c0 + 2*j);
        float2 b = *(const float2*)(ebr + layer*128 + c0 + 2*j);
        by[j] = make_float2(a.x + b.x, a.y + b.y);
        gv[j]  = *(const float2*)(eg  + layer*128 + c0 + 2*j);
        bev[j] = *(const float2*)(ebe + layer*128 + c0 + 2*j);
    }

    const int NTILES = ROWS_/64;
    for (int tile = blockIdx.x; tile < NTILES; tile += gridDim.x) {
        int row0 = tile*64;
        __syncthreads();
        {
            int r = tid >> 3, q0 = (tid & 7)*16;
            int rp = r >> 1, pr = r & 1, Gc = tid & 7;
            int rps = rp ^ Gc;
            const float* src = zin + (size_t)(row0 + r)*D_ + q0;
            #pragma unroll
            for (int q4 = 0; q4 < 16; q4 += 4) {
                float4 v = *(const float4*)(src + q4);
                int c = q0 + q4;
                ((float*)(xs + (c+0)*32 + rps))[pr] = v.x;
                ((float*)(xs + (c+1)*32 + rps))[pr] = v.y;
                ((float*)(xs + (c+2)*32 + rps))[pr] = v.z;
                ((float*)(xs + (c+3)*32 + rps))[pr] = v.w;
            }
        }
        __syncthreads();

        float2 ha[2][4], rc[2][4];
        #pragma unroll
        for (int j = 0; j < 4; j++) {
            ha[0][j] = bh[j]; ha[1][j] = bh[j];
            rc[0][j] = by[j]; rc[1][j] = by[j];
        }
        #pragma unroll 4
        for (int k = 0; k < 128; k++) {
            float2 xv = xs[k*32 + rpb + (rg ^ G8(k))];
            float4 wa = *(const float4*)(w1s + k*64 + cp0);
            float4 wa2 = *(const float4*)(w1s + k*64 + cp0 + 2);
            float4 wb = *(const float4*)(wrs + k*64 + cp0);
            float4 wb2 = *(const float4*)(wrs + k*64 + cp0 + 2);
            float2 xd0 = dupp(xv.x), xd1 = dupp(xv.y);
            ha[0][0] = ffma2(xd0, lo2(wa),  ha[0][0]);
            ha[1][0] = ffma2(xd1, lo2(wa),  ha[1][0]);
            ha[0][1] = ffma2(xd0, hi2(wa),  ha[0][1]);
            ha[1][1] = ffma2(xd1, hi2(wa),  ha[1][1]);
            ha[0][2] = ffma2(xd0, lo2(wa2), ha[0][2]);
            ha[1][2] = ffma2(xd1, lo2(wa2), ha[1][2]);
            ha[0][3] = ffma2(xd0, hi2(wa2), ha[0][3]);
            ha[1][3] = ffma2(xd1, hi2(wa2), ha[1][3]);
            rc[0][0] = ffma2(xd0, lo2(wb),  rc[0][0]);
            rc[1][0] = ffma2(xd1, lo2(wb),  rc[1][0]);
            rc[0][1] = ffma2(xd0, hi2(wb),  rc[0][1]);
            rc[1][1] = ffma2(xd1, hi2(wb),  rc[1][1]);
            rc[0][2] = ffma2(xd0, lo2(wb2), rc[0][2]);
            rc[1][2] = ffma2(xd1, lo2(wb2), rc[1][2]);
            rc[0][3] = ffma2(xd0, hi2(wb2), rc[0][3]);
            rc[1][3] = ffma2(xd1, hi2(wb2), rc[1][3]);
        }
        __syncthreads();

        {
            int rps = rpb + (rg ^ wcc);
            #pragma unroll
            for (int j = 0; j < 4; j++) {
                int ca = c0 + 2*j, cb = ca + 1;
                xs[ca*32 + rps] = make_float2(fmaxf(ha[0][j].x,0.f), fmaxf(ha[1][j].x,0.f));
                xs[cb*32 + rps] = make_float2(fmaxf(ha[0][j].y,0.f), fmaxf(ha[1][j].y,0.f));
            }
        }
        __syncthreads();

        #pragma unroll 4
        for (int k = 0; k < 128; k++) {
            float2 xv = xs[k*32 + rpb + (rg ^ G8(k))];
            float4 w0 = *(const float4*)(w2s + k*64 + cp0);
            float4 w02 = *(const float4*)(w2s + k*64 + cp0 + 2);
            float2 xd0 = dupp(xv.x), xd1 = dupp(xv.y);
            rc[0][0] = ffma2(xd0, lo2(w0),  rc[0][0]);
            rc[1][0] = ffma2(xd1, lo2(w0),  rc[1][0]);
            rc[0][1] = ffma2(xd0, hi2(w0),  rc[0][1]);
            rc[1][1] = ffma2(xd1, hi2(w0),  rc[1][1]);
            rc[0][2] = ffma2(xd0, lo2(w02), rc[0][2]);
            rc[1][2] = ffma2(xd1, lo2(w02), rc[1][2]);
            rc[0][3] = ffma2(xd0, hi2(w02), rc[0][3]);
            rc[1][3] = ffma2(xd1, hi2(w02), rc[1][3]);
        }
        __syncthreads();

        #pragma unroll
        for (int i = 0; i < 2; i++) {
            float s = 0.f, q = 0.f;
            #pragma unroll
            for (int j = 0; j < 4; j++) {
                s += rc[i][j].x + rc[i][j].y;
                q += rc[i][j].x*rc[i][j].x + rc[i][j].y*rc[i][j].y;
            }
            s += __shfl_xor_sync(0xffffffffu, s, 1);
            q += __shfl_xor_sync(0xffffffffu, q, 1);
            if (cg == 0) part[(r0+i)*8 + wcc] = make_float2(s, q);
        }
        __syncthreads();

        #pragma unroll
        for (int i = 0; i < 2; i++) {
            float s = 0.f, q = 0.f;
            #pragma unroll
            for (int w = 0; w < 8; w += 2) {
                float4 p = *(const float4*)(part + (r0+i)*8 + w);
                s += p.x + p.z; q += p.y + p.w;
            }
            float mu = s*(1.f/128.f);
            float rs = rsqrtf(q*(1.f/128.f) - mu*mu + EPS_);
            float4 o0, o1;
            o0.x = (rc[i][0].x - mu)*rs*gv[0].x + bev[0].x;
            o0.y = (rc[i][0].y - mu)*rs*gv[0].y + bev[0].y;
            o0.z = (rc[i][1].x - mu)*rs*gv[1].x + bev[1].x;
            o0.w = (rc[i][1].y - mu)*rs*gv[1].y + bev[1].y;
            o1.x = (rc[i][2].x - mu)*rs*gv[2].x + bev[2].x;
            o1.y = (rc[i][2].y - mu)*rs*gv[2].y + bev[2].y;
            o1.z = (rc[i][3].x - mu)*rs*gv[3].x + bev[3].x;
            o1.w = (rc[i][3].y - mu)*rs*gv[3].y + bev[3].y;
            float* op = zout + (size_t)(row0 + r0 + i)*D_ + c0;
            *(float4*)op       = o0;
            *(float4*)(op + 4) = o1;
        }
    }
}

// ============ K4: EMA recurrence + SiLU + transpose (unchanged) ============
__global__ void k4_ema(const float* __restrict__ omega)
{
    __shared__ float tile[128*65];
    int bn = blockIdx.x, d = threadIdx.x;
    float q0 = g_ema[d*4+0], a0 = g_ema[d*4+1];
    float q1 = g_ema[d*4+2], a1 = g_ema[d*4+3];
    float om = omega[d];
    const float* src = g_bufA + (size_t)bn*PNUM_*D_ + d;
    float* dst = g_u + (size_t)bn*KHEAD_;
    float s0 = 0.f, s1 = 0.f;
    for (int chunk = 0; chunk < 4; chunk++) {
        int tbase = chunk*64;
        int tn = (PNUM_ - tbase < 64) ? (PNUM_ - tbase) : 64;
        #pragma unroll 4
        for (int i = 0; i < tn; i++) {
            float xv = src[(size_t)(tbase + i)*D_];
            s0 = fmaf(s0, q0, xv);
            s1 = fmaf(s1, q1, xv);
            float v = fmaf(om, xv, fmaf(a0, s0, a1*s1));
            tile[d*65 + i] = v * (1.f/(1.f + __expf(-v)));
        }
        __syncthreads();
        for (int i = d; i < 128*64; i += 128) {
            int dd = i >> 6, tt = i & 63;
            if (tt < tn) dst[dd*PNUM_ + tbase + tt] = tile[dd*65 + tt];
        }
        __syncthreads();
    }
}

// ============ K5: head GEMM, grid 21x14 = 294 CTAs (one balanced wave) ============
__global__ void k5_init(const float* __restrict__ hb, float* __restrict__ out)
{
    int i = blockIdx.x*blockDim.x + threadIdx.x;
    if (i < BN_*PRED_) out[i] = hb[i % PRED_];
}

__global__ __launch_bounds__(192, 2)
void k5_head(const float* __restrict__ hw, float* __restrict__ out)
{
    __shared__ float u2[64*64];
    __shared__ float2 ws2[64*48];
    int tid = threadIdx.x;
    int cg = tid % 24, rg = tid / 24;
    int c0 = cg*4, r0 = rg*8;
    int row0 = blockIdx.x * 64;
    int y = blockIdx.y;                        // 14 k-splits: 6 of 37 chunks, 8 of 36
    int ch0 = (y < 6) ? y*37 : 222 + (y - 6)*36;
    int nch = (y < 6) ? 37 : 36;

    float2 acc[8][2];
    #pragma unroll
    for (int i = 0; i < 8; i++) { acc[i][0] = make_float2(0.f,0.f); acc[i][1] = make_float2(0.f,0.f); }

    for (int ch = 0; ch < nch; ch++) {
        int k0 = (ch0 + ch)*64;
        __syncthreads();
        for (int idx = tid; idx < 64*16; idx += 192) {
            int r = idx >> 4, q = (idx & 15)*4;
            float4 v = *(const float4*)(g_u + (size_t)(row0 + r)*KHEAD_ + k0 + q);
            int rr = r ^ SWR(q);
            u2[(q+0)*64 + rr] = v.x;
            u2[(q+1)*64 + rr] = v.y;
            u2[(q+2)*64 + rr] = v.z;
            u2[(q+3)*64 + rr] = v.w;
        }
        for (int idx = tid; idx < 64*48; idx += 192) {
            int k = idx / 48, s = idx - k*48;
            int cp = (s % 24)*2 + s/24;
            ws2[idx] = *(const float2*)(hw + (size_t)(k0 + k)*96 + 2*cp);
        }
        __syncthreads();
        #pragma unroll 2
        for (int kk = 0; kk < 64; kk++) {
            int rx = r0 ^ SWR(kk);
            float4 xa = *(const float4*)(u2 + kk*64 + rx);
            float4 xb = *(const float4*)(u2 + kk*64 + rx + 4);
            float2 w0 = ws2[kk*48 + cg];
            float2 w1v = ws2[kk*48 + 24 + cg];
            float2 xd[8] = {dup2(xa.x),dup2(xa.y),dup2(xa.z),dup2(xa.w),
                            dup2(xb.x),dup2(xb.y),dup2(xb.z),dup2(xb.w)};
            #pragma unroll
            for (int i = 0; i < 8; i++) {
                acc[i][0] = ffma2(xd[i], w0,  acc[i][0]);
                acc[i][1] = ffma2(xd[i], w1v, acc[i][1]);
            }
        }
    }
    #pragma unroll
    for (int i = 0; i < 8; i++) {
        float* op = out + (size_t)(row0 + r0 + i)*PRED_ + c0;
        atomicAdd(op+0, acc[i][0].x);
        atomicAdd(op+1, acc[i][0].y);
        atomicAdd(op+2, acc[i][1].x);
        atomicAdd(op+3, acc[i][1].y);
    }
}

// ============ launch ============
extern "C" void kernel_launch(void* const* d_in, const int* in_sizes, int n_in,
                              void* d_out, int out_size)
{
    const float* x       = (const float*)d_in[0];
    const float* fp_w1   = (const float*)d_in[1];
    const float* fp_b1   = (const float*)d_in[2];
    const float* fp_w2   = (const float*)d_in[3];
    const float* fp_b2   = (const float*)d_in[4];
    const float* fp_wr   = (const float*)d_in[5];
    const float* fp_br   = (const float*)d_in[6];
    const float* fp_g    = (const float*)d_in[7];
    const float* fp_be   = (const float*)d_in[8];
    const float* enc_w1  = (const float*)d_in[9];
    const float* enc_b1  = (const float*)d_in[10];
    const float* enc_w2  = (const float*)d_in[11];
    const float* enc_b2  = (const float*)d_in[12];
    const float* enc_wr  = (const float*)d_in[13];
    const float* enc_br  = (const float*)d_in[14];
    const float* enc_g   = (const float*)d_in[15];
    const float* enc_be  = (const float*)d_in[16];
    const float* e_delta = (const float*)d_in[17];
    const float* e_alpha = (const float*)d_in[18];
    const float* e_beta  = (const float*)d_in[19];
    const float* e_gamma = (const float*)d_in[20];
    const float* e_omega = (const float*)d_in[21];
    const float* head_w  = (const float*)d_in[22];
    const float* head_b  = (const float*)d_in[23];
    float* out = (float*)d_out;

    cudaFuncSetAttribute(k1_featproj, cudaFuncAttributeMaxDynamicSharedMemorySize, SM1_BYTES);
    cudaFuncSetAttribute(k2_encoder,  cudaFuncAttributeMaxDynamicSharedMemorySize, SM2_BYTES);

    k0_emaparam<<<1, 128>>>(e_delta, e_alpha, e_beta, e_gamma);
    k1_featproj<<<148, 512, SM1_BYTES>>>(x, fp_w1, fp_b1, fp_w2, fp_b2, fp_wr, fp_br, fp_g, fp_be);
    k2_encoder<<<148, 512, SM2_BYTES>>>(enc_w1, enc_b1, enc_w2, enc_b2, enc_wr, enc_br, enc_g, enc_be, 0);
    k2_encoder<<<148, 512, SM2_BYTES>>>(enc_w1, enc_b1, enc_w2, enc_b2, enc_wr, enc_br, enc_g, enc_be, 1);
    k4_ema<<<BN_, 128>>>(e_omega);
    k5_init<<<(BN_*PRED_ + 255)/256, 256>>>(head_b, out);
    k5_head<<<dim3(21, 14), 192>>>(head_w, out);
}